// round 1
// baseline (speedup 1.0000x reference)
#include <cuda_runtime.h>

#define NU 100000
#define NI 50000
#define NE 1600000
#define D  128

// ---------------- scratch (device globals: no allocations allowed) ----------
__device__ float g_inv_fs[NU];
__device__ float g_inv_fd[NU];
__device__ float g_inv_rs[NU];
__device__ float g_inv_rd[NI];
__device__ float g_inv_vs[NI];
__device__ float g_inv_vd[NU];

__device__ float g_hu1[(size_t)NU * D];  // user-source transformed feats (follows)
__device__ float g_hu2[(size_t)NU * D];  // user-source transformed feats (rates)
__device__ float g_hi [(size_t)NI * D];  // item-source transformed feats (rev)
__device__ float g_accu[(size_t)NU * D]; // layer-1 user accumulator
__device__ float g_acci[(size_t)NI * D]; // layer-1 item accumulator
__device__ float g_u  [(size_t)NU * D];  // layer-1 user output (post relu)
__device__ float g_it [(size_t)NI * D];  // layer-1 item output (post relu)

// ---------------- kernels ----------------------------------------------------

__global__ void k_zero_deg() {
    int i = blockIdx.x * blockDim.x + threadIdx.x;
    if (i < NU) {
        g_inv_fs[i] = 0.f; g_inv_fd[i] = 0.f;
        g_inv_rs[i] = 0.f; g_inv_vd[i] = 0.f;
    }
    if (i < NI) {
        g_inv_rd[i] = 0.f; g_inv_vs[i] = 0.f;
    }
}

__global__ void k_count(const int* __restrict__ src, const int* __restrict__ dst,
                        float* __restrict__ degs, float* __restrict__ degd) {
    int e = blockIdx.x * blockDim.x + threadIdx.x;
    if (e < NE) {
        atomicAdd(&degs[src[e]], 1.f);
        atomicAdd(&degd[dst[e]], 1.f);
    }
}

__device__ __forceinline__ float invsq(float x) { return x > 0.f ? rsqrtf(x) : 0.f; }

__global__ void k_inv() {
    int i = blockIdx.x * blockDim.x + threadIdx.x;
    if (i < NU) {
        g_inv_fs[i] = invsq(g_inv_fs[i]);
        g_inv_fd[i] = invsq(g_inv_fd[i]);
        g_inv_rs[i] = invsq(g_inv_rs[i]);
        g_inv_vd[i] = invsq(g_inv_vd[i]);
    }
    if (i < NI) {
        g_inv_rd[i] = invsq(g_inv_rd[i]);
        g_inv_vs[i] = invsq(g_inv_vs[i]);
    }
}

__global__ void k_zero(float4* __restrict__ p, int n4) {
    int i = blockIdx.x * blockDim.x + threadIdx.x;
    if (i < n4) p[i] = make_float4(0.f, 0.f, 0.f, 0.f);
}

// C[n,128] = A[n,128] @ W[128,128]  (row-major). 64 rows per block, 256 threads,
// each thread computes 8 rows x 4 cols. W + A tile staged in shared.
__global__ void __launch_bounds__(256) k_gemm(const float* __restrict__ A,
                                              const float* __restrict__ W,
                                              float* __restrict__ C, int n) {
    extern __shared__ float sm[];
    float* Ws = sm;              // 128*128 floats (64KB)
    float* As = sm + 128 * 128;  // 64*128 floats (32KB)

    for (int i = threadIdx.x; i < 128 * 32; i += 256)
        ((float4*)Ws)[i] = ((const float4*)W)[i];

    int row0 = blockIdx.x * 64;
    for (int i = threadIdx.x; i < 64 * 32; i += 256) {
        int r = i >> 5;
        int row = row0 + r;
        float4 v = (row < n) ? ((const float4*)A)[(size_t)row * 32 + (i & 31)]
                             : make_float4(0.f, 0.f, 0.f, 0.f);
        ((float4*)As)[i] = v;
    }
    __syncthreads();

    int ty = threadIdx.x >> 5;   // 0..7  -> rows ty*8 .. ty*8+7
    int tx = threadIdx.x & 31;   // 0..31 -> cols tx*4 .. tx*4+3
    float acc[8][4];
#pragma unroll
    for (int r = 0; r < 8; r++)
#pragma unroll
        for (int c = 0; c < 4; c++) acc[r][c] = 0.f;

    const float* a0 = As + ty * 8 * 128;
#pragma unroll 4
    for (int k = 0; k < 128; k++) {
        float4 w = ((const float4*)(Ws + k * 128))[tx];
#pragma unroll
        for (int r = 0; r < 8; r++) {
            float a = a0[r * 128 + k];
            acc[r][0] += a * w.x;
            acc[r][1] += a * w.y;
            acc[r][2] += a * w.z;
            acc[r][3] += a * w.w;
        }
    }

#pragma unroll
    for (int r = 0; r < 8; r++) {
        int row = row0 + ty * 8 + r;
        if (row < n)
            ((float4*)C)[(size_t)row * 32 + tx] =
                make_float4(acc[r][0], acc[r][1], acc[r][2], acc[r][3]);
    }
}

// One warp per edge: gather h[src] (float4/lane), scale by norm, vector-reduce
// into out[dst] with a single red.global.add.v4.f32 per lane.
__global__ void k_scatter(const int* __restrict__ src, const int* __restrict__ dst,
                          const float* __restrict__ invs, const float* __restrict__ invd,
                          const float* __restrict__ h, float* __restrict__ out) {
    int t = blockIdx.x * blockDim.x + threadIdx.x;
    int e = t >> 5;
    if (e >= NE) return;
    int lane = threadIdx.x & 31;
    int s  = src[e];
    int dd = dst[e];
    float w = invs[s] * invd[dd];
    float4 v = ((const float4*)(h + (size_t)s * D))[lane];
    float* o = out + (size_t)dd * D + lane * 4;
    asm volatile("red.global.add.v4.f32 [%0], {%1, %2, %3, %4};"
                 :: "l"(o), "f"(v.x * w), "f"(v.y * w), "f"(v.z * w), "f"(v.w * w)
                 : "memory");
}

// layer-1 epilogue: u = relu(0.5*(accu + b1f + b1v)); it = relu(acci + b1r)
__global__ void k_epi1(const float* __restrict__ b1f, const float* __restrict__ b1v,
                       const float* __restrict__ b1r) {
    int i = blockIdx.x * blockDim.x + threadIdx.x;
    int c = i & (D - 1);
    if (i < NU * D) {
        g_u[i] = fmaxf(0.5f * (g_accu[i] + b1f[c] + b1v[c]), 0.f);
    } else if (i < (NU + NI) * D) {
        int j = i - NU * D;
        g_it[j] = fmaxf(g_acci[j] + b1r[c], 0.f);
    }
}

// layer-2 epilogue (in place on d_out): users *0.5 + biases; items + bias
__global__ void k_epi2(float* __restrict__ out, const float* __restrict__ b2f,
                       const float* __restrict__ b2v, const float* __restrict__ b2r) {
    int i = blockIdx.x * blockDim.x + threadIdx.x;
    int c = i & (D - 1);
    if (i < NU * D) {
        out[i] = 0.5f * (out[i] + b2f[c] + b2v[c]);
    } else if (i < (NU + NI) * D) {
        out[i] = out[i] + b2r[c];
    }
}

// ---------------- host driver ------------------------------------------------

extern "C" void kernel_launch(void* const* d_in, const int* in_sizes, int n_in,
                              void* d_out, int out_size) {
    const float* x_user = (const float*)d_in[0];
    const float* x_item = (const float*)d_in[1];
    const int* f_src = (const int*)d_in[2];
    const int* f_dst = (const int*)d_in[3];
    const int* r_src = (const int*)d_in[4];
    const int* r_dst = (const int*)d_in[5];
    const int* v_src = (const int*)d_in[6];
    const int* v_dst = (const int*)d_in[7];

    const float *W1f, *W1r, *W1v, *W2f, *W2r, *W2v;
    const float *b1f, *b1r, *b1v, *b2f, *b2r, *b2v;
    if (in_sizes[9] == 128 * 128) {
        // dict order: W1f,W1r,W1v,W2f,W2r,W2v then b1f,b1r,b1v,b2f,b2r,b2v
        W1f = (const float*)d_in[8];  W1r = (const float*)d_in[9];  W1v = (const float*)d_in[10];
        W2f = (const float*)d_in[11]; W2r = (const float*)d_in[12]; W2v = (const float*)d_in[13];
        b1f = (const float*)d_in[14]; b1r = (const float*)d_in[15]; b1v = (const float*)d_in[16];
        b2f = (const float*)d_in[17]; b2r = (const float*)d_in[18]; b2v = (const float*)d_in[19];
    } else {
        // signature order: (W,b) interleaved
        W1f = (const float*)d_in[8];  b1f = (const float*)d_in[9];
        W1r = (const float*)d_in[10]; b1r = (const float*)d_in[11];
        W1v = (const float*)d_in[12]; b1v = (const float*)d_in[13];
        W2f = (const float*)d_in[14]; b2f = (const float*)d_in[15];
        W2r = (const float*)d_in[16]; b2r = (const float*)d_in[17];
        W2v = (const float*)d_in[18]; b2v = (const float*)d_in[19];
    }
    float* out = (float*)d_out;

    // resolve scratch addresses (pure host-side queries; capture-safe)
    float *inv_fs, *inv_fd, *inv_rs, *inv_rd, *inv_vs, *inv_vd;
    float *hu1, *hu2, *hi, *accu, *acci, *u, *it;
    cudaGetSymbolAddress((void**)&inv_fs, g_inv_fs);
    cudaGetSymbolAddress((void**)&inv_fd, g_inv_fd);
    cudaGetSymbolAddress((void**)&inv_rs, g_inv_rs);
    cudaGetSymbolAddress((void**)&inv_rd, g_inv_rd);
    cudaGetSymbolAddress((void**)&inv_vs, g_inv_vs);
    cudaGetSymbolAddress((void**)&inv_vd, g_inv_vd);
    cudaGetSymbolAddress((void**)&hu1, g_hu1);
    cudaGetSymbolAddress((void**)&hu2, g_hu2);
    cudaGetSymbolAddress((void**)&hi,  g_hi);
    cudaGetSymbolAddress((void**)&accu, g_accu);
    cudaGetSymbolAddress((void**)&acci, g_acci);
    cudaGetSymbolAddress((void**)&u,  g_u);
    cudaGetSymbolAddress((void**)&it, g_it);

    const int TB = 256;
    const int GEMM_SMEM = (128 * 128 + 64 * 128) * (int)sizeof(float);  // 96KB
    cudaFuncSetAttribute(k_gemm, cudaFuncAttributeMaxDynamicSharedMemorySize, GEMM_SMEM);

    int gNU   = (NU + TB - 1) / TB;
    int gEdge = (NE + TB - 1) / TB;
    int gScat = (NE * 32 + TB - 1) / TB;   // one warp per edge
    int gAll  = ((NU + NI) * D + TB - 1) / TB;

    // --- degrees -> inverse-sqrt norms ---
    k_zero_deg<<<gNU, TB>>>();
    k_count<<<gEdge, TB>>>(f_src, f_dst, inv_fs, inv_fd);
    k_count<<<gEdge, TB>>>(r_src, r_dst, inv_rs, inv_rd);
    k_count<<<gEdge, TB>>>(v_src, v_dst, inv_vs, inv_vd);
    k_inv<<<gNU, TB>>>();

    // --- layer 1 GEMMs ---
    k_gemm<<<(NU + 63) / 64, 256, GEMM_SMEM>>>(x_user, W1f, hu1, NU);
    k_gemm<<<(NU + 63) / 64, 256, GEMM_SMEM>>>(x_user, W1r, hu2, NU);
    k_gemm<<<(NI + 63) / 64, 256, GEMM_SMEM>>>(x_item, W1v, hi,  NI);

    // --- layer 1 propagation ---
    k_zero<<<(NU * D / 4 + TB - 1) / TB, TB>>>((float4*)accu, NU * D / 4);
    k_zero<<<(NI * D / 4 + TB - 1) / TB, TB>>>((float4*)acci, NI * D / 4);
    k_scatter<<<gScat, TB>>>(f_src, f_dst, inv_fs, inv_fd, hu1, accu);
    k_scatter<<<gScat, TB>>>(v_src, v_dst, inv_vs, inv_vd, hi,  accu);
    k_scatter<<<gScat, TB>>>(r_src, r_dst, inv_rs, inv_rd, hu2, acci);
    k_epi1<<<gAll, TB>>>(b1f, b1v, b1r);

    // --- layer 2 GEMMs (reuse h buffers) ---
    k_gemm<<<(NU + 63) / 64, 256, GEMM_SMEM>>>(u,  W2f, hu1, NU);
    k_gemm<<<(NU + 63) / 64, 256, GEMM_SMEM>>>(u,  W2r, hu2, NU);
    k_gemm<<<(NI + 63) / 64, 256, GEMM_SMEM>>>(it, W2v, hi,  NI);

    // --- layer 2 propagation straight into d_out ---
    k_zero<<<((NU + NI) * D / 4 + TB - 1) / TB, TB>>>((float4*)out, (NU + NI) * D / 4);
    k_scatter<<<gScat, TB>>>(f_src, f_dst, inv_fs, inv_fd, hu1, out);
    k_scatter<<<gScat, TB>>>(v_src, v_dst, inv_vs, inv_vd, hi,  out);
    k_scatter<<<gScat, TB>>>(r_src, r_dst, inv_rs, inv_rd, hu2, out + (size_t)NU * D);
    k_epi2<<<gAll, TB>>>(out, b2f, b2v, b2r);
}

// round 2
// speedup vs baseline: 1.9790x; 1.9790x over previous
#include <cuda_runtime.h>

#define NU 100000
#define NI 50000
#define NE 1600000
#define D  128

// ---------------- scratch (device globals) ----------------------------------
// degree histograms (int) per relation endpoint
__device__ int g_h_fs[NU];
__device__ int g_h_fd[NU];
__device__ int g_h_rs[NU];
__device__ int g_h_rd[NI];
__device__ int g_h_vs[NI];
__device__ int g_h_vd[NU];
// inverse-sqrt norms
__device__ float g_inv_fs[NU];
__device__ float g_inv_fd[NU];
__device__ float g_inv_rs[NU];
__device__ float g_inv_rd[NI];
__device__ float g_inv_vs[NI];
__device__ float g_inv_vd[NU];
// CSR (sorted by dst): offsets, fill cursors, per-edge src + src-norm
__device__ int   g_off_f[NU + 1];
__device__ int   g_off_r[NI + 1];
__device__ int   g_off_v[NU + 1];
__device__ int   g_pos_f[NU];
__device__ int   g_pos_r[NI];
__device__ int   g_pos_v[NU];
__device__ int   g_srcs_f[NE];
__device__ int   g_srcs_r[NE];
__device__ int   g_srcs_v[NE];
__device__ float g_ws_f[NE];
__device__ float g_ws_r[NE];
__device__ float g_ws_v[NE];
__device__ int   g_bsum[1024];
// feature buffers
__device__ float g_hu1[(size_t)NU * D];
__device__ float g_hu2[(size_t)NU * D];
__device__ float g_hi [(size_t)NI * D];
__device__ float g_u  [(size_t)NU * D];
__device__ float g_it [(size_t)NI * D];

// ---------------- setup kernels ----------------------------------------------

__global__ void k_zero_hists() {
    int i = blockIdx.x * blockDim.x + threadIdx.x;
    if (i < NU) { g_h_fs[i] = 0; g_h_fd[i] = 0; g_h_rs[i] = 0; g_h_vd[i] = 0; }
    if (i < NI) { g_h_rd[i] = 0; g_h_vs[i] = 0; }
}

__global__ void k_hist(const int* __restrict__ src, const int* __restrict__ dst,
                       int* __restrict__ hs, int* __restrict__ hd) {
    int e = blockIdx.x * blockDim.x + threadIdx.x;
    if (e < NE) {
        atomicAdd(&hs[src[e]], 1);
        atomicAdd(&hd[dst[e]], 1);
    }
}

__device__ __forceinline__ float invsq(int x) {
    return x > 0 ? rsqrtf((float)x) : 0.f;
}

__global__ void k_inv_all() {
    int i = blockIdx.x * blockDim.x + threadIdx.x;
    if (i < NU) {
        g_inv_fs[i] = invsq(g_h_fs[i]);
        g_inv_fd[i] = invsq(g_h_fd[i]);
        g_inv_rs[i] = invsq(g_h_rs[i]);
        g_inv_vd[i] = invsq(g_h_vd[i]);
    }
    if (i < NI) {
        g_inv_rd[i] = invsq(g_h_rd[i]);
        g_inv_vs[i] = invsq(g_h_vs[i]);
    }
}

// ---------------- exclusive scan (3-kernel) -----------------------------------

__global__ void k_scan1(const int* __restrict__ in, int* __restrict__ out,
                        int* __restrict__ bsums, int n) {
    __shared__ int s[1024];
    int tid = threadIdx.x;
    int i = blockIdx.x * 1024 + tid;
    int v = (i < n) ? in[i] : 0;
    s[tid] = v;
    __syncthreads();
#pragma unroll
    for (int o = 1; o < 1024; o <<= 1) {
        int t = (tid >= o) ? s[tid - o] : 0;
        __syncthreads();
        s[tid] += t;
        __syncthreads();
    }
    if (i < n) out[i] = s[tid] - v;
    if (tid == 1023) bsums[blockIdx.x] = s[1023];
}

__global__ void k_scan2(int* __restrict__ b, int nb) {
    __shared__ int s[1024];
    int tid = threadIdx.x;
    int v = (tid < nb) ? b[tid] : 0;
    s[tid] = v;
    __syncthreads();
#pragma unroll
    for (int o = 1; o < 1024; o <<= 1) {
        int t = (tid >= o) ? s[tid - o] : 0;
        __syncthreads();
        s[tid] += t;
        __syncthreads();
    }
    if (tid < nb) b[tid] = s[tid] - v;
}

__global__ void k_scan3(int* __restrict__ out, const int* __restrict__ bsums,
                        int n, int total) {
    int i = blockIdx.x * blockDim.x + threadIdx.x;
    if (i < n) out[i] += bsums[i >> 10];
    else if (i == n) out[n] = total;
}

__global__ void k_fill(const int* __restrict__ src, const int* __restrict__ dst,
                       const float* __restrict__ invs, int* __restrict__ pos,
                       int* __restrict__ srcs_out, float* __restrict__ ws_out) {
    int e = blockIdx.x * blockDim.x + threadIdx.x;
    if (e < NE) {
        int d = dst[e];
        int s = src[e];
        int p = atomicAdd(&pos[d], 1);
        srcs_out[p] = s;
        ws_out[p] = invs[s];
    }
}

// ---------------- GEMM: C[n,128] = A[n,128] @ W[128,128], packed f32x2 --------

__global__ void __launch_bounds__(256) k_gemm(const float* __restrict__ A,
                                              const float* __restrict__ W,
                                              float* __restrict__ C, int n) {
    extern __shared__ float sm[];
    float* Ws = sm;              // 128*128 floats
    float* As = sm + 128 * 128;  // 64*128 floats

    for (int i = threadIdx.x; i < 128 * 32; i += 256)
        ((float4*)Ws)[i] = ((const float4*)W)[i];

    int row0 = blockIdx.x * 64;
    for (int i = threadIdx.x; i < 64 * 32; i += 256) {
        int r = i >> 5;
        int row = row0 + r;
        float4 v = (row < n) ? ((const float4*)A)[(size_t)row * 32 + (i & 31)]
                             : make_float4(0.f, 0.f, 0.f, 0.f);
        ((float4*)As)[i] = v;
    }
    __syncthreads();

    int ty = threadIdx.x >> 5;
    int tx = threadIdx.x & 31;

    unsigned long long acc[8][2];
#pragma unroll
    for (int r = 0; r < 8; r++) { acc[r][0] = 0ull; acc[r][1] = 0ull; }

    const float* a0 = As + ty * 8 * 128;
#pragma unroll 4
    for (int k = 0; k < 128; k++) {
        ulonglong2 w = ((const ulonglong2*)(Ws + k * 128))[tx];
#pragma unroll
        for (int r = 0; r < 8; r++) {
            float a = a0[r * 128 + k];
            unsigned long long aa;
            asm("mov.b64 %0, {%1, %1};" : "=l"(aa) : "f"(a));
            asm("fma.rn.f32x2 %0, %1, %2, %0;" : "+l"(acc[r][0]) : "l"(aa), "l"(w.x));
            asm("fma.rn.f32x2 %0, %1, %2, %0;" : "+l"(acc[r][1]) : "l"(aa), "l"(w.y));
        }
    }

#pragma unroll
    for (int r = 0; r < 8; r++) {
        int row = row0 + ty * 8 + r;
        if (row < n) {
            float4 o;
            asm("mov.b64 {%0, %1}, %2;" : "=f"(o.x), "=f"(o.y) : "l"(acc[r][0]));
            asm("mov.b64 {%0, %1}, %2;" : "=f"(o.z), "=f"(o.w) : "l"(acc[r][1]));
            ((float4*)C)[(size_t)row * 32 + tx] = o;
        }
    }
}

// ---------------- CSR gather-aggregate ----------------------------------------

__device__ __forceinline__ float4 agg_list(const float* __restrict__ h,
                                           const int* __restrict__ srcs,
                                           const float* __restrict__ ws,
                                           int j, int end, int lane) {
    float x = 0.f, y = 0.f, z = 0.f, w = 0.f;
    for (; j + 1 < end; j += 2) {
        int s0 = __ldg(srcs + j);
        int s1 = __ldg(srcs + j + 1);
        float w0 = __ldg(ws + j);
        float w1 = __ldg(ws + j + 1);
        float4 v0 = __ldg((const float4*)(h + (size_t)s0 * D) + lane);
        float4 v1 = __ldg((const float4*)(h + (size_t)s1 * D) + lane);
        x += w0 * v0.x + w1 * v1.x;
        y += w0 * v0.y + w1 * v1.y;
        z += w0 * v0.z + w1 * v1.z;
        w += w0 * v0.w + w1 * v1.w;
    }
    if (j < end) {
        int s0 = __ldg(srcs + j);
        float w0 = __ldg(ws + j);
        float4 v0 = __ldg((const float4*)(h + (size_t)s0 * D) + lane);
        x += w0 * v0.x; y += w0 * v0.y; z += w0 * v0.z; w += w0 * v0.w;
    }
    return make_float4(x, y, z, w);
}

// User-dst: fused (follows + rev), out = [relu](0.5*(fd*accF + vd*accV + bF + bV))
template <bool RELU>
__global__ void __launch_bounds__(256) k_agg_user(
    const float* __restrict__ hF, const float* __restrict__ hV,
    const float* __restrict__ bF, const float* __restrict__ bV,
    float* __restrict__ outp) {
    int warp = (blockIdx.x * blockDim.x + threadIdx.x) >> 5;
    if (warp >= NU) return;
    int lane = threadIdx.x & 31;

    float4 aF = agg_list(hF, g_srcs_f, g_ws_f, g_off_f[warp], g_off_f[warp + 1], lane);
    float4 aV = agg_list(hV, g_srcs_v, g_ws_v, g_off_v[warp], g_off_v[warp + 1], lane);
    float fF = g_inv_fd[warp];
    float fV = g_inv_vd[warp];
    float4 b1 = __ldg((const float4*)bF + lane);
    float4 b2 = __ldg((const float4*)bV + lane);

    float4 o;
    o.x = 0.5f * (fF * aF.x + fV * aV.x + b1.x + b2.x);
    o.y = 0.5f * (fF * aF.y + fV * aV.y + b1.y + b2.y);
    o.z = 0.5f * (fF * aF.z + fV * aV.z + b1.z + b2.z);
    o.w = 0.5f * (fF * aF.w + fV * aV.w + b1.w + b2.w);
    if (RELU) {
        o.x = fmaxf(o.x, 0.f); o.y = fmaxf(o.y, 0.f);
        o.z = fmaxf(o.z, 0.f); o.w = fmaxf(o.w, 0.f);
    }
    ((float4*)outp)[(size_t)warp * 32 + lane] = o;
}

// Item-dst (rates): out = [relu](rd*acc + b)
template <bool RELU>
__global__ void __launch_bounds__(256) k_agg_item(
    const float* __restrict__ h, const float* __restrict__ b,
    float* __restrict__ outp) {
    int warp = (blockIdx.x * blockDim.x + threadIdx.x) >> 5;
    if (warp >= NI) return;
    int lane = threadIdx.x & 31;

    float4 a = agg_list(h, g_srcs_r, g_ws_r, g_off_r[warp], g_off_r[warp + 1], lane);
    float f = g_inv_rd[warp];
    float4 bb = __ldg((const float4*)b + lane);

    float4 o;
    o.x = f * a.x + bb.x;
    o.y = f * a.y + bb.y;
    o.z = f * a.z + bb.z;
    o.w = f * a.w + bb.w;
    if (RELU) {
        o.x = fmaxf(o.x, 0.f); o.y = fmaxf(o.y, 0.f);
        o.z = fmaxf(o.z, 0.f); o.w = fmaxf(o.w, 0.f);
    }
    ((float4*)outp)[(size_t)warp * 32 + lane] = o;
}

// ---------------- host driver --------------------------------------------------

extern "C" void kernel_launch(void* const* d_in, const int* in_sizes, int n_in,
                              void* d_out, int out_size) {
    const float* x_user = (const float*)d_in[0];
    const float* x_item = (const float*)d_in[1];
    const int* f_src = (const int*)d_in[2];
    const int* f_dst = (const int*)d_in[3];
    const int* r_src = (const int*)d_in[4];
    const int* r_dst = (const int*)d_in[5];
    const int* v_src = (const int*)d_in[6];
    const int* v_dst = (const int*)d_in[7];

    const float *W1f, *W1r, *W1v, *W2f, *W2r, *W2v;
    const float *b1f, *b1r, *b1v, *b2f, *b2r, *b2v;
    if (in_sizes[9] == 128 * 128) {
        W1f = (const float*)d_in[8];  W1r = (const float*)d_in[9];  W1v = (const float*)d_in[10];
        W2f = (const float*)d_in[11]; W2r = (const float*)d_in[12]; W2v = (const float*)d_in[13];
        b1f = (const float*)d_in[14]; b1r = (const float*)d_in[15]; b1v = (const float*)d_in[16];
        b2f = (const float*)d_in[17]; b2r = (const float*)d_in[18]; b2v = (const float*)d_in[19];
    } else {
        W1f = (const float*)d_in[8];  b1f = (const float*)d_in[9];
        W1r = (const float*)d_in[10]; b1r = (const float*)d_in[11];
        W1v = (const float*)d_in[12]; b1v = (const float*)d_in[13];
        W2f = (const float*)d_in[14]; b2f = (const float*)d_in[15];
        W2r = (const float*)d_in[16]; b2r = (const float*)d_in[17];
        W2v = (const float*)d_in[18]; b2v = (const float*)d_in[19];
    }
    float* out = (float*)d_out;

    // resolve scratch addresses
    float *inv_fs, *inv_rs, *inv_vs;
    int *h_fs, *h_fd, *h_rs, *h_rd, *h_vs, *h_vd;
    int *off_f, *off_r, *off_v, *pos_f, *pos_r, *pos_v, *bsum;
    int *srcs_f, *srcs_r, *srcs_v;
    float *ws_f, *ws_r, *ws_v;
    float *hu1, *hu2, *hi, *u, *it;
    cudaGetSymbolAddress((void**)&inv_fs, g_inv_fs);
    cudaGetSymbolAddress((void**)&inv_rs, g_inv_rs);
    cudaGetSymbolAddress((void**)&inv_vs, g_inv_vs);
    cudaGetSymbolAddress((void**)&h_fs, g_h_fs);
    cudaGetSymbolAddress((void**)&h_fd, g_h_fd);
    cudaGetSymbolAddress((void**)&h_rs, g_h_rs);
    cudaGetSymbolAddress((void**)&h_rd, g_h_rd);
    cudaGetSymbolAddress((void**)&h_vs, g_h_vs);
    cudaGetSymbolAddress((void**)&h_vd, g_h_vd);
    cudaGetSymbolAddress((void**)&off_f, g_off_f);
    cudaGetSymbolAddress((void**)&off_r, g_off_r);
    cudaGetSymbolAddress((void**)&off_v, g_off_v);
    cudaGetSymbolAddress((void**)&pos_f, g_pos_f);
    cudaGetSymbolAddress((void**)&pos_r, g_pos_r);
    cudaGetSymbolAddress((void**)&pos_v, g_pos_v);
    cudaGetSymbolAddress((void**)&bsum, g_bsum);
    cudaGetSymbolAddress((void**)&srcs_f, g_srcs_f);
    cudaGetSymbolAddress((void**)&srcs_r, g_srcs_r);
    cudaGetSymbolAddress((void**)&srcs_v, g_srcs_v);
    cudaGetSymbolAddress((void**)&ws_f, g_ws_f);
    cudaGetSymbolAddress((void**)&ws_r, g_ws_r);
    cudaGetSymbolAddress((void**)&ws_v, g_ws_v);
    cudaGetSymbolAddress((void**)&hu1, g_hu1);
    cudaGetSymbolAddress((void**)&hu2, g_hu2);
    cudaGetSymbolAddress((void**)&hi,  g_hi);
    cudaGetSymbolAddress((void**)&u,  g_u);
    cudaGetSymbolAddress((void**)&it, g_it);

    const int TB = 256;
    const int GEMM_SMEM = (128 * 128 + 64 * 128) * (int)sizeof(float);
    cudaFuncSetAttribute(k_gemm, cudaFuncAttributeMaxDynamicSharedMemorySize, GEMM_SMEM);

    int gNU   = (NU + TB - 1) / TB;
    int gEdge = (NE + TB - 1) / TB;
    int gAggU = (NU * 32 + TB - 1) / TB;
    int gAggI = (NI * 32 + TB - 1) / TB;

    // --- histograms / norms ---
    k_zero_hists<<<gNU, TB>>>();
    k_hist<<<gEdge, TB>>>(f_src, f_dst, h_fs, h_fd);
    k_hist<<<gEdge, TB>>>(r_src, r_dst, h_rs, h_rd);
    k_hist<<<gEdge, TB>>>(v_src, v_dst, h_vs, h_vd);
    k_inv_all<<<gNU, TB>>>();

    // --- CSR offsets (exclusive scan of dst histograms) ---
    int nbU = (NU + 1023) / 1024, nbI = (NI + 1023) / 1024;
    k_scan1<<<nbU, 1024>>>(h_fd, off_f, bsum, NU);
    k_scan2<<<1, 1024>>>(bsum, nbU);
    k_scan3<<<(NU + 1 + TB - 1) / TB, TB>>>(off_f, bsum, NU, NE);

    k_scan1<<<nbI, 1024>>>(h_rd, off_r, bsum, NI);
    k_scan2<<<1, 1024>>>(bsum, nbI);
    k_scan3<<<(NI + 1 + TB - 1) / TB, TB>>>(off_r, bsum, NI, NE);

    k_scan1<<<nbU, 1024>>>(h_vd, off_v, bsum, NU);
    k_scan2<<<1, 1024>>>(bsum, nbU);
    k_scan3<<<(NU + 1 + TB - 1) / TB, TB>>>(off_v, bsum, NU, NE);

    // --- fill CSR (src + src-side norm, sorted by dst) ---
    cudaMemcpyAsync(pos_f, off_f, NU * sizeof(int), cudaMemcpyDeviceToDevice);
    cudaMemcpyAsync(pos_r, off_r, NI * sizeof(int), cudaMemcpyDeviceToDevice);
    cudaMemcpyAsync(pos_v, off_v, NU * sizeof(int), cudaMemcpyDeviceToDevice);
    k_fill<<<gEdge, TB>>>(f_src, f_dst, inv_fs, pos_f, srcs_f, ws_f);
    k_fill<<<gEdge, TB>>>(r_src, r_dst, inv_rs, pos_r, srcs_r, ws_r);
    k_fill<<<gEdge, TB>>>(v_src, v_dst, inv_vs, pos_v, srcs_v, ws_v);

    // --- layer 1 ---
    k_gemm<<<(NU + 63) / 64, 256, GEMM_SMEM>>>(x_user, W1f, hu1, NU);
    k_gemm<<<(NU + 63) / 64, 256, GEMM_SMEM>>>(x_user, W1r, hu2, NU);
    k_gemm<<<(NI + 63) / 64, 256, GEMM_SMEM>>>(x_item, W1v, hi,  NI);
    k_agg_user<true><<<gAggU, TB>>>(hu1, hi, b1f, b1v, u);
    k_agg_item<true><<<gAggI, TB>>>(hu2, b1r, it);

    // --- layer 2 ---
    k_gemm<<<(NU + 63) / 64, 256, GEMM_SMEM>>>(u,  W2f, hu1, NU);
    k_gemm<<<(NU + 63) / 64, 256, GEMM_SMEM>>>(u,  W2r, hu2, NU);
    k_gemm<<<(NI + 63) / 64, 256, GEMM_SMEM>>>(it, W2v, hi,  NI);
    k_agg_user<false><<<gAggU, TB>>>(hu1, hi, b2f, b2v, out);
    k_agg_item<false><<<gAggI, TB>>>(hu2, b2r, out + (size_t)NU * D);
}